// round 2
// baseline (speedup 1.0000x reference)
#include <cuda_runtime.h>
#include <math.h>

// Problem constants (fixed by the dataset)
#define B_  4
#define LP_ 256
#define LW_ 200
#define D_  768
#define D4_ (D_/4)        // 192 float4 per row
#define W_  4             // words per block
#define WBLK_ (LW_/W_)    // 50 word-blocks per batch

#define MIN_BLOCKS 192

__device__ float g_partial_min[MIN_BLOCKS];
__device__ float g_min_val;

// ---------------- global-min reduction (pass 1) ----------------
__global__ void partial_min_kernel(const float4* __restrict__ x, int n4) {
    float m = INFINITY;
    for (int i = blockIdx.x * blockDim.x + threadIdx.x; i < n4;
         i += gridDim.x * blockDim.x) {
        float4 v = x[i];
        m = fminf(m, fminf(fminf(v.x, v.y), fminf(v.z, v.w)));
    }
    __shared__ float s[256];
    int t = threadIdx.x;
    s[t] = m;
    __syncthreads();
    for (int off = 128; off > 0; off >>= 1) {
        if (t < off) s[t] = fminf(s[t], s[t + off]);
        __syncthreads();
    }
    if (t == 0) g_partial_min[blockIdx.x] = s[0];
}

// ---------------- global-min reduction (pass 2) ----------------
__global__ void final_min_kernel() {
    int t = threadIdx.x;
    float m = (t < MIN_BLOCKS) ? g_partial_min[t] : INFINITY;
    __shared__ float s[256];
    s[t] = m;
    __syncthreads();
    for (int off = 128; off > 0; off >>= 1) {
        if (t < off) s[t] = fminf(s[t], s[t + off]);
        __syncthreads();
    }
    if (t == 0) g_min_val = s[0];
}

// ---------------- main: masked max-pool, W_ words per block ----------------
// grid: B_*WBLK_ blocks (200), block: 192 threads (1 float4 of D per thread)
__global__ __launch_bounds__(D4_) void word_max_kernel(
    const float* __restrict__ emb,      // [B, Lp, D]
    const int*   __restrict__ p2w,      // [B, Lw, Lp]
    float*       __restrict__ out)      // [B, Lw, D]
{
    const int blk = blockIdx.x;
    const int b   = blk / WBLK_;
    const int w0  = (blk % WBLK_) * W_;
    const int tid = threadIdx.x;        // 0..191 -> float4 index in D

    // Build per-piece bitmap: bit j set iff word (w0+j) owns piece p.
    __shared__ unsigned char smask[LP_];
    for (int p = tid; p < LP_; p += D4_) {
        unsigned m = 0;
        #pragma unroll
        for (int j = 0; j < W_; j++) {
            m |= (p2w[((b * LW_ + w0 + j) * LP_) + p] != 0) ? (1u << j) : 0u;
        }
        smask[p] = (unsigned char)m;
    }
    __syncthreads();

    const float gmin = g_min_val;
    float4 acc[W_];
    #pragma unroll
    for (int j = 0; j < W_; j++) acc[j] = make_float4(gmin, gmin, gmin, gmin);

    // emb rows for this batch, this thread's float4 slot
    const float4* erow = reinterpret_cast<const float4*>(emb)
                         + (size_t)b * LP_ * D4_ + tid;

    #pragma unroll 4
    for (int p = 0; p < LP_; p++) {
        unsigned m = smask[p];          // block-uniform -> no divergence
        if (m) {
            float4 v = erow[(size_t)p * D4_];
            #pragma unroll
            for (int j = 0; j < W_; j++) {
                if (m & (1u << j)) {
                    acc[j].x = fmaxf(acc[j].x, v.x);
                    acc[j].y = fmaxf(acc[j].y, v.y);
                    acc[j].z = fmaxf(acc[j].z, v.z);
                    acc[j].w = fmaxf(acc[j].w, v.w);
                }
            }
        }
    }

    float4* out4 = reinterpret_cast<float4*>(out)
                   + ((size_t)(b * LW_ + w0)) * D4_ + tid;
    #pragma unroll
    for (int j = 0; j < W_; j++) out4[(size_t)j * D4_] = acc[j];
}

extern "C" void kernel_launch(void* const* d_in, const int* in_sizes, int n_in,
                              void* d_out, int out_size) {
    const float* emb = (const float*)d_in[0];   // [4,256,768] f32
    const int*   p2w = (const int*)d_in[1];     // [4,200,256] i32
    float*       out = (float*)d_out;           // [4,200,768] f32

    const int n4 = (B_ * LP_ * D_) / 4;
    partial_min_kernel<<<MIN_BLOCKS, 256>>>((const float4*)emb, n4);
    final_min_kernel<<<1, 256>>>();
    word_max_kernel<<<B_ * WBLK_, D4_>>>(emb, p2w, out);
}

// round 5
// speedup vs baseline: 2.6388x; 2.6388x over previous
#include <cuda_runtime.h>
#include <math.h>

// Problem constants (fixed by the dataset)
#define B_   4
#define LP_  256
#define LW_  200
#define D_   768
#define D4_  (D_/4)      // 192 float4 per row
#define NCH_ 37          // word-chunks per batch (15 chunks of 6 + 22 chunks of 5)
#define WMAX_ 6
#define NT_  384         // threads per block (2 piece-halves x 192 d-threads)

#define MIN_BLOCKS 256

__device__ float g_partial_min[MIN_BLOCKS];

// ---------------- global-min partial reduction ----------------
__global__ void partial_min_kernel(const float4* __restrict__ x, int n4) {
    float m = INFINITY;
    for (int i = blockIdx.x * blockDim.x + threadIdx.x; i < n4;
         i += gridDim.x * blockDim.x) {
        float4 v = x[i];
        m = fminf(m, fminf(fminf(v.x, v.y), fminf(v.z, v.w)));
    }
    __shared__ float s[256];
    int t = threadIdx.x;
    s[t] = m;
    __syncthreads();
    for (int off = 128; off > 0; off >>= 1) {
        if (t < off) s[t] = fminf(s[t], s[t + off]);
        __syncthreads();
    }
    if (t == 0) g_partial_min[blockIdx.x] = s[0];
}

// ---------------- main: masked max-pool ----------------
// grid: exactly 148 blocks = 4 batches x 37 word-chunks (one block per SM).
// block: 384 threads = {piece-half 0: pieces 0..127, half 1: 128..255} x 192 d-slots.
__global__ __launch_bounds__(NT_) void word_max_kernel(
    const float* __restrict__ emb,      // [B, Lp, D]
    const int*   __restrict__ p2w,      // [B, Lw, Lp]
    float*       __restrict__ out)      // [B, Lw, D]
{
    __shared__ float  sred[NT_];
    __shared__ unsigned char smask[LP_];        // bit j: word w0+j owns piece p
    __shared__ float4 sacc[WMAX_][D4_];         // half-1 partials

    const int tid = threadIdx.x;
    const int blk = blockIdx.x;
    const int b   = blk / NCH_;
    const int c   = blk % NCH_;
    const int w0  = (c < 15) ? c * 6 : 90 + (c - 15) * 5;
    const int nw  = (c < 15) ? 6 : 5;

    // --- reduce global min from partials (redundant per block, cheap) ---
    sred[tid] = (tid < MIN_BLOCKS) ? g_partial_min[tid] : INFINITY;
    __syncthreads();
    if (tid < 128) sred[tid] = fminf(sred[tid], sred[tid + 128]);
    __syncthreads();
    for (int off = 64; off > 0; off >>= 1) {
        if (tid < off) sred[tid] = fminf(sred[tid], sred[tid + off]);
        __syncthreads();
    }

    // --- build per-piece mask bitmap ---
    for (int p = tid; p < LP_; p += NT_) {
        unsigned m = 0;
        const int* row = p2w + ((size_t)(b * LW_ + w0)) * LP_ + p;
        #pragma unroll
        for (int j = 0; j < WMAX_; j++) {
            if (j < nw && row[(size_t)j * LP_] != 0) m |= (1u << j);
        }
        smask[p] = (unsigned char)m;
    }
    __syncthreads();

    const float gmin = sred[0];
    const int half = tid / D4_;      // 0 or 1
    const int dt   = tid % D4_;      // float4 slot in D
    const int p0   = half * (LP_ / 2);

    float4 acc[WMAX_];
    #pragma unroll
    for (int j = 0; j < WMAX_; j++) acc[j] = make_float4(gmin, gmin, gmin, gmin);

    const float4* erow = reinterpret_cast<const float4*>(emb)
                         + (size_t)b * LP_ * D4_ + dt;

    // 128 pieces per half, processed 4 at a time: 4 unconditional loads
    // (high MLP), then mask-predicated fmax.
    for (int p = p0; p < p0 + LP_ / 2; p += 4) {
        unsigned mq = *reinterpret_cast<const unsigned*>(&smask[p]);
        float4 v0 = erow[(size_t)(p + 0) * D4_];
        float4 v1 = erow[(size_t)(p + 1) * D4_];
        float4 v2 = erow[(size_t)(p + 2) * D4_];
        float4 v3 = erow[(size_t)(p + 3) * D4_];

        #pragma unroll
        for (int q = 0; q < 4; q++) {
            float4 v = (q == 0) ? v0 : (q == 1) ? v1 : (q == 2) ? v2 : v3;
            unsigned m = (mq >> (8 * q)) & 0xFFu;
            #pragma unroll
            for (int j = 0; j < WMAX_; j++) {
                if (m & (1u << j)) {
                    acc[j].x = fmaxf(acc[j].x, v.x);
                    acc[j].y = fmaxf(acc[j].y, v.y);
                    acc[j].z = fmaxf(acc[j].z, v.z);
                    acc[j].w = fmaxf(acc[j].w, v.w);
                }
            }
        }
    }

    // --- combine halves and store ---
    if (half == 1) {
        #pragma unroll
        for (int j = 0; j < WMAX_; j++)
            if (j < nw) sacc[j][dt] = acc[j];
    }
    __syncthreads();
    if (half == 0) {
        float4* out4 = reinterpret_cast<float4*>(out)
                       + ((size_t)(b * LW_ + w0)) * D4_ + dt;
        #pragma unroll
        for (int j = 0; j < WMAX_; j++) {
            if (j < nw) {
                float4 o = sacc[j][dt];
                o.x = fmaxf(o.x, acc[j].x);
                o.y = fmaxf(o.y, acc[j].y);
                o.z = fmaxf(o.z, acc[j].z);
                o.w = fmaxf(o.w, acc[j].w);
                out4[(size_t)j * D4_] = o;
            }
        }
    }
}

extern "C" void kernel_launch(void* const* d_in, const int* in_sizes, int n_in,
                              void* d_out, int out_size) {
    const float* emb = (const float*)d_in[0];   // [4,256,768] f32
    const int*   p2w = (const int*)d_in[1];     // [4,200,256] i32
    float*       out = (float*)d_out;           // [4,200,768] f32

    const int n4 = (B_ * LP_ * D_) / 4;
    partial_min_kernel<<<MIN_BLOCKS, 256>>>((const float4*)emb, n4);
    word_max_kernel<<<B_ * NCH_, NT_>>>(emb, p2w, out);
}